// round 13
// baseline (speedup 1.0000x reference)
#include <cuda_runtime.h>
#include <cuda_bf16.h>
#include <cstdint>

#define NUM_CLASSES 1000
#define CPAD        1024                   // padded class count
#define FEAT_DIM    256
#define N_ROWS      262144
#define ALPHA       0.5f
#define HB          64                     // index blocks (all co-resident)
#define IT          512                    // index block threads
#define ROWS_PER_HB (N_ROWS / HB)          // 4096
#define RPT         (ROWS_PER_HB / IT)     // 8 rows per thread
#define CHUNK       512                    // rows per gather block
#define NCHUNK      (N_ROWS / CHUNK)       // 512 gather blocks

// Scratch (device globals — no allocation allowed).
__device__ int g_parthist[HB * CPAD];
__device__ int g_offsets[NUM_CLASSES];
__device__ int g_counts[NUM_CLASSES];
__device__ int g_rowidx[N_ROWS];
__device__ __align__(16) float g_sums[NUM_CLASSES * FEAT_DIM];
__device__ unsigned g_cnt1 = 0, g_gen1 = 0;

// Spin barrier among the 64 co-resident index blocks (self-resetting).
__device__ __forceinline__ void spin_barrier(unsigned* cnt, unsigned* gen, unsigned nb) {
    __syncthreads();
    if (threadIdx.x == 0) {
        __threadfence();
        unsigned g = atomicAdd(gen, 0u);
        unsigned old = atomicAdd(cnt, 1u);
        if (old == nb - 1) {
            atomicExch(cnt, 0u);
            __threadfence();
            atomicAdd(gen, 1u);
        } else {
            while (atomicAdd(gen, 0u) == g) __nanosleep(64);
        }
        __threadfence();
    }
    __syncthreads();
}

#define F4ADD(a, b) { (a).x += (b).x; (a).y += (b).y; (a).z += (b).z; (a).w += (b).w; }

__device__ __forceinline__ void red_add_v4(float* addr, float4 v) {
    asm volatile("red.global.add.v4.f32 [%0], {%1, %2, %3, %4};"
                 :: "l"(addr), "f"(v.x), "f"(v.y), "f"(v.z), "f"(v.w)
                 : "memory");
}

// ---------------------------------------------------------------------------
// K1: index build — 512 threads/block, int2-vectorized Phase B.
// Also zeros g_sums for the RED accumulation.
// ---------------------------------------------------------------------------
__global__ void __launch_bounds__(IT)
index_kernel(const int* __restrict__ labels) {
    __shared__ int shA[CPAD];   // phase A: histogram; phase B: scatter bases
    __shared__ int shS[IT];     // phase B: block scan of per-thread sums

    int tid = threadIdx.x;
    int myB = blockIdx.x;

    // Zero the RED accumulator (1 MB spread over 64 blocks).
    {
        float4* s4 = reinterpret_cast<float4*>(g_sums);
        int total4 = NUM_CLASSES * FEAT_DIM / 4;          // 64000
        for (int i = myB * IT + tid; i < total4; i += HB * IT)
            s4[i] = make_float4(0.f, 0.f, 0.f, 0.f);
    }

    // --- Phase A: histogram + ranks (held in registers) ---
    for (int c = tid; c < CPAD; c += IT) shA[c] = 0;
    __syncthreads();

    const int4* __restrict__ lab4 = reinterpret_cast<const int4*>(labels);
    int base4 = myB * (ROWS_PER_HB / 4);                  // 1024 int4/block

    int lab[RPT], rnk[RPT];
#pragma unroll
    for (int k = 0; k < RPT / 4; k++) {                   // 2 int4 loads
        int4 L = lab4[base4 + tid + k * IT];
        lab[k * 4 + 0] = L.x; lab[k * 4 + 1] = L.y;
        lab[k * 4 + 2] = L.z; lab[k * 4 + 3] = L.w;
    }
#pragma unroll
    for (int e = 0; e < RPT; e++) rnk[e] = atomicAdd(&shA[lab[e]], 1);
    __syncthreads();

    for (int c = tid; c < CPAD; c += IT)
        g_parthist[myB * CPAD + c] = shA[c];

    // --- Barrier: all partial histograms visible ---
    spin_barrier(&g_cnt1, &g_gen1, HB);

    // --- Phase B: each thread owns classes (2*tid, 2*tid+1); int2 sweep ---
    int c0 = tid * 2;
    int tot0 = 0, tot1 = 0, pre0 = 0, pre1 = 0;
    const int2* __restrict__ ph2 = reinterpret_cast<const int2*>(g_parthist);
#pragma unroll 8
    for (int b = 0; b < HB; b++) {
        int2 v = ph2[b * (CPAD / 2) + tid];
        tot0 += v.x;
        tot1 += v.y;
        if (b < myB) { pre0 += v.x; pre1 += v.y; }
    }

    // Block-wide exclusive scan over per-thread sums (class order == tid order).
    int mysum = tot0 + tot1;
    shS[tid] = mysum;
    __syncthreads();
#pragma unroll
    for (int off = 1; off < IT; off <<= 1) {
        int v = (tid >= off) ? shS[tid - off] : 0;
        __syncthreads();
        shS[tid] += v;
        __syncthreads();
    }
    int e0 = shS[tid] - mysum;          // exclusive offset of class c0
    int e1 = e0 + tot0;

    if (myB == 0) {                     // publish for chunksum/finalize
        if (c0 + 0 < NUM_CLASSES) { g_offsets[c0 + 0] = e0; g_counts[c0 + 0] = tot0; }
        if (c0 + 1 < NUM_CLASSES) { g_offsets[c0 + 1] = e1; g_counts[c0 + 1] = tot1; }
    }

    // This block's scatter base per class.
    shA[c0 + 0] = e0 + pre0;
    shA[c0 + 1] = e1 + pre1;
    __syncthreads();

    // --- Place: register-held rows straight to class-sorted order ---
    int rowbase = myB * ROWS_PER_HB;
#pragma unroll
    for (int k = 0; k < RPT / 4; k++) {
#pragma unroll
        for (int e = 0; e < 4; e++) {
            int idx = k * 4 + e;
            int row = rowbase + (tid + k * IT) * 4 + e;
            g_rowidx[shA[lab[idx]] + rnk[idx]] = row;
        }
    }
}

// ---------------------------------------------------------------------------
// K2: perfectly balanced gather — each block owns CHUNK consecutive entries
// of the class-sorted rowidx. Per class segment: accumulate, smem cross-slot
// reduce, one v4-RED per 16B of the class sum. (Unchanged — measured.)
// ---------------------------------------------------------------------------
__global__ void __launch_bounds__(256, 4)
chunksum_kernel(const float* __restrict__ features) {
    __shared__ float4 sred[256];
    int tid = threadIdx.x;
    int r4 = tid >> 6;   // row slot 0..3
    int c4 = tid & 63;   // float4 column 0..63
    const float4* __restrict__ f4 = reinterpret_cast<const float4*>(features);

    int s = blockIdx.x * CHUNK;
    int e = s + CHUNK;

    // Largest cls with offsets[cls] <= s  (offsets[0] == 0).
    int lo = 0, hi = NUM_CLASSES - 1;
    while (lo < hi) {
        int mid = (lo + hi + 1) >> 1;
        if (g_offsets[mid] <= s) lo = mid; else hi = mid - 1;
    }
    int cls = lo;
    int pos = s;

    while (pos < e) {
        while (cls < NUM_CLASSES - 1 && g_offsets[cls + 1] <= pos) cls++;
        int cend = g_offsets[cls] + g_counts[cls];
        int segend = min(e, cend);

        float4 a0 = make_float4(0.f, 0.f, 0.f, 0.f);
        float4 a1 = a0, a2 = a0, a3 = a0;

        int i = pos + r4;
        for (; i + 12 < segend; i += 16) {
            int i0 = g_rowidx[i];
            int i1 = g_rowidx[i + 4];
            int i2 = g_rowidx[i + 8];
            int i3 = g_rowidx[i + 12];
            float4 v0 = __ldcs(&f4[(size_t)i0 * 64 + c4]);
            float4 v1 = __ldcs(&f4[(size_t)i1 * 64 + c4]);
            float4 v2 = __ldcs(&f4[(size_t)i2 * 64 + c4]);
            float4 v3 = __ldcs(&f4[(size_t)i3 * 64 + c4]);
            F4ADD(a0, v0); F4ADD(a1, v1); F4ADD(a2, v2); F4ADD(a3, v3);
        }
        for (; i < segend; i += 4) {
            float4 v = __ldcs(&f4[(size_t)g_rowidx[i] * 64 + c4]);
            F4ADD(a0, v);
        }
        F4ADD(a0, a1); F4ADD(a2, a3); F4ADD(a0, a2);

        sred[tid] = a0;
        __syncthreads();
        if (tid < 64) {
            float4 t0 = sred[tid];
            float4 t1 = sred[tid + 64];
            float4 t2 = sred[tid + 128];
            float4 t3 = sred[tid + 192];
            F4ADD(t0, t1); F4ADD(t2, t3); F4ADD(t0, t2);
            red_add_v4(&g_sums[(size_t)cls * FEAT_DIM + tid * 4], t0);
        }
        __syncthreads();
        pos = segend;
    }
}

// ---------------------------------------------------------------------------
// K3: finalize — mean + EMA + output (64000 float4s).
// ---------------------------------------------------------------------------
__global__ void __launch_bounds__(256)
finalize_kernel(const float* __restrict__ centers, float* __restrict__ out) {
    int i = blockIdx.x * blockDim.x + threadIdx.x;      // float4 index
    if (i >= NUM_CLASSES * FEAT_DIM / 4) return;
    int cls = i >> 6;
    int n = g_counts[cls];
    float4 c = reinterpret_cast<const float4*>(centers)[i];
    float4 o = c;
    if (n > 0) {
        float4 t = reinterpret_cast<const float4*>(g_sums)[i];
        float scale = ALPHA / (float)n;
        o.x = (1.0f - ALPHA) * c.x + scale * t.x;
        o.y = (1.0f - ALPHA) * c.y + scale * t.y;
        o.z = (1.0f - ALPHA) * c.z + scale * t.z;
        o.w = (1.0f - ALPHA) * c.w + scale * t.w;
    }
    reinterpret_cast<float4*>(out)[i] = o;
}

// ---------------------------------------------------------------------------
// Launch: features f32 [N,256], labels i32 [N], centers f32 [1000,256].
// ---------------------------------------------------------------------------
extern "C" void kernel_launch(void* const* d_in, const int* in_sizes, int n_in,
                              void* d_out, int out_size) {
    const float* features = (const float*)d_in[0];
    const int* labels     = (const int*)d_in[1];
    const float* centers  = (const float*)d_in[2];
    float* out            = (float*)d_out;

    index_kernel<<<HB, IT>>>(labels);
    chunksum_kernel<<<NCHUNK, 256>>>(features);
    finalize_kernel<<<(NUM_CLASSES * FEAT_DIM / 4 + 255) / 256, 256>>>(centers, out);
}

// round 14
// speedup vs baseline: 1.1220x; 1.1220x over previous
#include <cuda_runtime.h>
#include <cuda_bf16.h>
#include <cstdint>

#define NUM_CLASSES 1000
#define CPAD        1024                   // padded class count
#define FEAT_DIM    256
#define N_ROWS      262144
#define ALPHA       0.5f
#define NB          256                    // index blocks (2/SM co-resident)
#define NT          256                    // index block threads
#define ROWS_PER_B  (N_ROWS / NB)          // 1024
#define CHUNK       512                    // rows per gather block
#define NCHUNK      (N_ROWS / CHUNK)       // 512 gather blocks

// Scratch (device globals — no allocation allowed).
__device__ int g_parthist_t[CPAD * NB];    // [class][block] — transposed
__device__ int g_blockbase[NB * CPAD];     // [block][class]
__device__ int g_totals[CPAD];
__device__ int g_offsets[NUM_CLASSES];
__device__ int g_counts[NUM_CLASSES];
__device__ int g_rowidx[N_ROWS];
__device__ __align__(16) float g_sums[NUM_CLASSES * FEAT_DIM];
__device__ unsigned g_cnt1 = 0, g_gen1 = 0;
__device__ unsigned g_cnt2 = 0, g_gen2 = 0;

// Spin barrier among the NB co-resident blocks (self-resetting, replay-safe).
__device__ __forceinline__ void spin_barrier(unsigned* cnt, unsigned* gen, unsigned nb) {
    __syncthreads();
    if (threadIdx.x == 0) {
        __threadfence();
        unsigned g = atomicAdd(gen, 0u);
        unsigned old = atomicAdd(cnt, 1u);
        if (old == nb - 1) {
            atomicExch(cnt, 0u);
            __threadfence();
            atomicAdd(gen, 1u);
        } else {
            while (atomicAdd(gen, 0u) == g) __nanosleep(64);
        }
        __threadfence();
    }
    __syncthreads();
}

#define F4ADD(a, b) { (a).x += (b).x; (a).y += (b).y; (a).z += (b).z; (a).w += (b).w; }

__device__ __forceinline__ void red_add_v4(float* addr, float4 v) {
    asm volatile("red.global.add.v4.f32 [%0], {%1, %2, %3, %4};"
                 :: "l"(addr), "f"(v.x), "f"(v.y), "f"(v.z), "f"(v.w)
                 : "memory");
}

// ---------------------------------------------------------------------------
// K1: index build — 256 blocks. A: hist+rank. B: distributed cross-block
// scan (4 classes/block). C: local offsets scan + place. Zeros g_sums too.
// ---------------------------------------------------------------------------
__global__ void __launch_bounds__(NT, 2)
index_kernel(const int* __restrict__ labels) {
    __shared__ int shA[CPAD];   // A: histogram; C: scatter bases
    __shared__ int shW[8];      // B: per-warp segment totals
    __shared__ int shS[NT];     // C: block scan

    int tid = threadIdx.x;
    int myB = blockIdx.x;

    // Zero the RED accumulator (64000 float4 over 65536 threads).
    {
        int i = myB * NT + tid;
        if (i < NUM_CLASSES * FEAT_DIM / 4)
            reinterpret_cast<float4*>(g_sums)[i] = make_float4(0.f, 0.f, 0.f, 0.f);
    }

    // --- Phase A: histogram + ranks (held in registers) ---
#pragma unroll
    for (int c = tid; c < CPAD; c += NT) shA[c] = 0;
    __syncthreads();

    // Each thread owns rows myB*1024 + tid*4 .. +3 (one int4).
    int4 L = reinterpret_cast<const int4*>(labels)[myB * (ROWS_PER_B / 4) + tid];
    int lab[4] = {L.x, L.y, L.z, L.w};
    int rnk[4];
#pragma unroll
    for (int e = 0; e < 4; e++) rnk[e] = atomicAdd(&shA[lab[e]], 1);
    __syncthreads();

    // Write partial histogram transposed: [class][block].
#pragma unroll
    for (int c = tid; c < CPAD; c += NT)
        g_parthist_t[c * NB + myB] = shA[c];

    spin_barrier(&g_cnt1, &g_gen1, NB);

    // --- Phase B: cross-block scan. Block owns classes myB*4+j (j=0..3);
    // 64 threads per class, thread t covers blocks 4t..4t+3 (int4, coalesced).
    {
        int j = tid >> 6;          // class slot 0..3
        int t = tid & 63;          // thread within class group
        int c = myB * 4 + j;
        int4 v = *reinterpret_cast<const int4*>(&g_parthist_t[c * NB + 4 * t]);
        int s = v.x + v.y + v.z + v.w;

        // Inclusive shfl-scan within warp; segment = 2 warps per class.
        int lane = t & 31;
        int inc = s;
#pragma unroll
        for (int off = 1; off < 32; off <<= 1) {
            int u = __shfl_up_sync(0xFFFFFFFFu, inc, off);
            if (lane >= off) inc += u;
        }
        if (lane == 31) shW[tid >> 5] = inc;   // per-warp total
        __syncthreads();
        int segbase = (t >= 32) ? shW[(tid >> 5) - 1] : 0;
        int excl = segbase + inc - s;          // exclusive prefix over blocks

        g_blockbase[(4 * t + 0) * CPAD + c] = excl;
        g_blockbase[(4 * t + 1) * CPAD + c] = excl + v.x;
        g_blockbase[(4 * t + 2) * CPAD + c] = excl + v.x + v.y;
        g_blockbase[(4 * t + 3) * CPAD + c] = excl + v.x + v.y + v.z;
        if (t == 63) g_totals[c] = excl + s;
    }

    spin_barrier(&g_cnt2, &g_gen2, NB);

    // --- Phase C: local scan of class totals -> offsets; bases; place. ---
    int4 T = *reinterpret_cast<const int4*>(&g_totals[tid * 4]);
    int mysum = T.x + T.y + T.z + T.w;
    shS[tid] = mysum;
    __syncthreads();
#pragma unroll
    for (int off = 1; off < NT; off <<= 1) {
        int v = (tid >= off) ? shS[tid - off] : 0;
        __syncthreads();
        shS[tid] += v;
        __syncthreads();
    }
    int e0 = shS[tid] - mysum;
    int e1 = e0 + T.x, e2 = e1 + T.y, e3 = e2 + T.z;

    if (myB == 0) {                 // publish for chunksum/finalize
        int c4 = tid * 4;
        if (c4 + 0 < NUM_CLASSES) { g_offsets[c4 + 0] = e0; g_counts[c4 + 0] = T.x; }
        if (c4 + 1 < NUM_CLASSES) { g_offsets[c4 + 1] = e1; g_counts[c4 + 1] = T.y; }
        if (c4 + 2 < NUM_CLASSES) { g_offsets[c4 + 2] = e2; g_counts[c4 + 2] = T.z; }
        if (c4 + 3 < NUM_CLASSES) { g_offsets[c4 + 3] = e3; g_counts[c4 + 3] = T.w; }
    }

    // This block's scatter bases (coalesced int4 read of its blockbase row).
    int4 B = *reinterpret_cast<const int4*>(&g_blockbase[myB * CPAD + tid * 4]);
    shA[tid * 4 + 0] = e0 + B.x;
    shA[tid * 4 + 1] = e1 + B.y;
    shA[tid * 4 + 2] = e2 + B.z;
    shA[tid * 4 + 3] = e3 + B.w;
    __syncthreads();

    // Place register-held rows straight to class-sorted order.
    int rowbase = myB * ROWS_PER_B + tid * 4;
#pragma unroll
    for (int e = 0; e < 4; e++)
        g_rowidx[shA[lab[e]] + rnk[e]] = rowbase + e;
}

// ---------------------------------------------------------------------------
// K2: perfectly balanced gather — each block owns CHUNK consecutive entries
// of the class-sorted rowidx. (Unchanged — measured.)
// ---------------------------------------------------------------------------
__global__ void __launch_bounds__(256, 4)
chunksum_kernel(const float* __restrict__ features) {
    __shared__ float4 sred[256];
    int tid = threadIdx.x;
    int r4 = tid >> 6;   // row slot 0..3
    int c4 = tid & 63;   // float4 column 0..63
    const float4* __restrict__ f4 = reinterpret_cast<const float4*>(features);

    int s = blockIdx.x * CHUNK;
    int e = s + CHUNK;

    // Largest cls with offsets[cls] <= s  (offsets[0] == 0).
    int lo = 0, hi = NUM_CLASSES - 1;
    while (lo < hi) {
        int mid = (lo + hi + 1) >> 1;
        if (g_offsets[mid] <= s) lo = mid; else hi = mid - 1;
    }
    int cls = lo;
    int pos = s;

    while (pos < e) {
        while (cls < NUM_CLASSES - 1 && g_offsets[cls + 1] <= pos) cls++;
        int cend = g_offsets[cls] + g_counts[cls];
        int segend = min(e, cend);

        float4 a0 = make_float4(0.f, 0.f, 0.f, 0.f);
        float4 a1 = a0, a2 = a0, a3 = a0;

        int i = pos + r4;
        for (; i + 12 < segend; i += 16) {
            int i0 = g_rowidx[i];
            int i1 = g_rowidx[i + 4];
            int i2 = g_rowidx[i + 8];
            int i3 = g_rowidx[i + 12];
            float4 v0 = __ldcs(&f4[(size_t)i0 * 64 + c4]);
            float4 v1 = __ldcs(&f4[(size_t)i1 * 64 + c4]);
            float4 v2 = __ldcs(&f4[(size_t)i2 * 64 + c4]);
            float4 v3 = __ldcs(&f4[(size_t)i3 * 64 + c4]);
            F4ADD(a0, v0); F4ADD(a1, v1); F4ADD(a2, v2); F4ADD(a3, v3);
        }
        for (; i < segend; i += 4) {
            float4 v = __ldcs(&f4[(size_t)g_rowidx[i] * 64 + c4]);
            F4ADD(a0, v);
        }
        F4ADD(a0, a1); F4ADD(a2, a3); F4ADD(a0, a2);

        sred[tid] = a0;
        __syncthreads();
        if (tid < 64) {
            float4 t0 = sred[tid];
            float4 t1 = sred[tid + 64];
            float4 t2 = sred[tid + 128];
            float4 t3 = sred[tid + 192];
            F4ADD(t0, t1); F4ADD(t2, t3); F4ADD(t0, t2);
            red_add_v4(&g_sums[(size_t)cls * FEAT_DIM + tid * 4], t0);
        }
        __syncthreads();
        pos = segend;
    }
}

// ---------------------------------------------------------------------------
// K3: finalize — mean + EMA + output (64000 float4s).
// ---------------------------------------------------------------------------
__global__ void __launch_bounds__(256)
finalize_kernel(const float* __restrict__ centers, float* __restrict__ out) {
    int i = blockIdx.x * blockDim.x + threadIdx.x;      // float4 index
    if (i >= NUM_CLASSES * FEAT_DIM / 4) return;
    int cls = i >> 6;
    int n = g_counts[cls];
    float4 c = reinterpret_cast<const float4*>(centers)[i];
    float4 o = c;
    if (n > 0) {
        float4 t = reinterpret_cast<const float4*>(g_sums)[i];
        float scale = ALPHA / (float)n;
        o.x = (1.0f - ALPHA) * c.x + scale * t.x;
        o.y = (1.0f - ALPHA) * c.y + scale * t.y;
        o.z = (1.0f - ALPHA) * c.z + scale * t.z;
        o.w = (1.0f - ALPHA) * c.w + scale * t.w;
    }
    reinterpret_cast<float4*>(out)[i] = o;
}

// ---------------------------------------------------------------------------
// Launch: features f32 [N,256], labels i32 [N], centers f32 [1000,256].
// ---------------------------------------------------------------------------
extern "C" void kernel_launch(void* const* d_in, const int* in_sizes, int n_in,
                              void* d_out, int out_size) {
    const float* features = (const float*)d_in[0];
    const int* labels     = (const int*)d_in[1];
    const float* centers  = (const float*)d_in[2];
    float* out            = (float*)d_out;

    index_kernel<<<NB, NT>>>(labels);
    chunksum_kernel<<<NCHUNK, 256>>>(features);
    finalize_kernel<<<(NUM_CLASSES * FEAT_DIM / 4 + 255) / 256, 256>>>(centers, out);
}

// round 15
// speedup vs baseline: 1.1290x; 1.0062x over previous
#include <cuda_runtime.h>
#include <cuda_bf16.h>
#include <cstdint>

#define NUM_CLASSES 1000
#define CPAD        1024                   // padded class count
#define FEAT_DIM    256
#define N_ROWS      262144
#define ALPHA       0.5f
#define NB          256                    // index blocks
#define NT          256                    // index block threads
#define ROWS_PER_B  (N_ROWS / NB)          // 1024
#define CHUNK       512                    // rows per gather block
#define NCHUNK      (N_ROWS / CHUNK)       // 512 gather blocks

// Scratch (device globals — no allocation allowed).
__device__ int g_parthist_t[CPAD * NB];    // [class][block] — transposed
__device__ int g_blockbase[NB * CPAD];     // [block][class]
__device__ int g_totals[CPAD];
__device__ int g_offsets[NUM_CLASSES];
__device__ int g_counts[NUM_CLASSES];
__device__ int g_rank[N_ROWS];
__device__ int g_rowidx[N_ROWS];
__device__ __align__(16) float g_sums[NUM_CLASSES * FEAT_DIM];

#define F4ADD(a, b) { (a).x += (b).x; (a).y += (b).y; (a).z += (b).z; (a).w += (b).w; }

__device__ __forceinline__ void red_add_v4(float* addr, float4 v) {
    asm volatile("red.global.add.v4.f32 [%0], {%1, %2, %3, %4};"
                 :: "l"(addr), "f"(v.x), "f"(v.y), "f"(v.z), "f"(v.w)
                 : "memory");
}

// ---------------------------------------------------------------------------
// K_A: per-block smem histogram + within-(block,class) ranks -> g_rank.
// Writes the partial histogram transposed [class][block]. Zeros g_sums.
// ---------------------------------------------------------------------------
__global__ void __launch_bounds__(NT)
idxA_kernel(const int* __restrict__ labels) {
    __shared__ int shA[CPAD];
    int tid = threadIdx.x;
    int myB = blockIdx.x;

    // Zero the RED accumulator (64000 float4 across 65536 threads).
    {
        int i = myB * NT + tid;
        if (i < NUM_CLASSES * FEAT_DIM / 4)
            reinterpret_cast<float4*>(g_sums)[i] = make_float4(0.f, 0.f, 0.f, 0.f);
    }

#pragma unroll
    for (int c = tid; c < CPAD; c += NT) shA[c] = 0;
    __syncthreads();

    int4 L = reinterpret_cast<const int4*>(labels)[myB * (ROWS_PER_B / 4) + tid];
    int4 R;
    R.x = atomicAdd(&shA[L.x], 1);
    R.y = atomicAdd(&shA[L.y], 1);
    R.z = atomicAdd(&shA[L.z], 1);
    R.w = atomicAdd(&shA[L.w], 1);
    reinterpret_cast<int4*>(g_rank)[myB * (ROWS_PER_B / 4) + tid] = R;
    __syncthreads();

#pragma unroll
    for (int c = tid; c < CPAD; c += NT)
        g_parthist_t[c * NB + myB] = shA[c];
}

// ---------------------------------------------------------------------------
// K_B: distributed cross-block scan. Block owns classes myB*4+j (j=0..3);
// 64 threads per class, thread t covers blocks 4t..4t+3 (int4, coalesced).
// Produces per-(block,class) bases and per-class totals.
// ---------------------------------------------------------------------------
__global__ void __launch_bounds__(NT)
idxB_kernel() {
    __shared__ int shW[8];
    int tid = threadIdx.x;
    int myB = blockIdx.x;

    int j = tid >> 6;          // class slot 0..3
    int t = tid & 63;          // thread within class group
    int c = myB * 4 + j;
    int4 v = *reinterpret_cast<const int4*>(&g_parthist_t[c * NB + 4 * t]);
    int s = v.x + v.y + v.z + v.w;

    // Inclusive shfl-scan within warp; segment = 2 warps per class.
    int lane = t & 31;
    int inc = s;
#pragma unroll
    for (int off = 1; off < 32; off <<= 1) {
        int u = __shfl_up_sync(0xFFFFFFFFu, inc, off);
        if (lane >= off) inc += u;
    }
    if (lane == 31) shW[tid >> 5] = inc;   // per-warp total
    __syncthreads();
    int segbase = (t >= 32) ? shW[(tid >> 5) - 1] : 0;
    int excl = segbase + inc - s;          // exclusive prefix over blocks

    g_blockbase[(4 * t + 0) * CPAD + c] = excl;
    g_blockbase[(4 * t + 1) * CPAD + c] = excl + v.x;
    g_blockbase[(4 * t + 2) * CPAD + c] = excl + v.x + v.y;
    g_blockbase[(4 * t + 3) * CPAD + c] = excl + v.x + v.y + v.z;
    if (t == 63) g_totals[c] = excl + s;
}

// ---------------------------------------------------------------------------
// K_C: local scan of class totals -> offsets; scatter bases; place.
// ---------------------------------------------------------------------------
__global__ void __launch_bounds__(NT)
idxC_kernel(const int* __restrict__ labels) {
    __shared__ int shA[CPAD];   // scatter bases
    __shared__ int shS[NT];     // block scan
    int tid = threadIdx.x;
    int myB = blockIdx.x;

    int4 T = *reinterpret_cast<const int4*>(&g_totals[tid * 4]);
    int mysum = T.x + T.y + T.z + T.w;
    shS[tid] = mysum;
    __syncthreads();
#pragma unroll
    for (int off = 1; off < NT; off <<= 1) {
        int v = (tid >= off) ? shS[tid - off] : 0;
        __syncthreads();
        shS[tid] += v;
        __syncthreads();
    }
    int e0 = shS[tid] - mysum;
    int e1 = e0 + T.x, e2 = e1 + T.y, e3 = e2 + T.z;

    if (myB == 0) {                 // publish for chunksum/finalize
        int c4 = tid * 4;
        if (c4 + 0 < NUM_CLASSES) { g_offsets[c4 + 0] = e0; g_counts[c4 + 0] = T.x; }
        if (c4 + 1 < NUM_CLASSES) { g_offsets[c4 + 1] = e1; g_counts[c4 + 1] = T.y; }
        if (c4 + 2 < NUM_CLASSES) { g_offsets[c4 + 2] = e2; g_counts[c4 + 2] = T.z; }
        if (c4 + 3 < NUM_CLASSES) { g_offsets[c4 + 3] = e3; g_counts[c4 + 3] = T.w; }
    }

    // This block's scatter bases (coalesced int4 read of its blockbase row).
    int4 B = *reinterpret_cast<const int4*>(&g_blockbase[myB * CPAD + tid * 4]);
    shA[tid * 4 + 0] = e0 + B.x;
    shA[tid * 4 + 1] = e1 + B.y;
    shA[tid * 4 + 2] = e2 + B.z;
    shA[tid * 4 + 3] = e3 + B.w;
    __syncthreads();

    // Place rows straight to class-sorted order (labels/ranks L2-hot).
    int4 L = reinterpret_cast<const int4*>(labels)[myB * (ROWS_PER_B / 4) + tid];
    int4 R = reinterpret_cast<const int4*>(g_rank)[myB * (ROWS_PER_B / 4) + tid];
    int rowbase = myB * ROWS_PER_B + tid * 4;
    g_rowidx[shA[L.x] + R.x] = rowbase + 0;
    g_rowidx[shA[L.y] + R.y] = rowbase + 1;
    g_rowidx[shA[L.z] + R.z] = rowbase + 2;
    g_rowidx[shA[L.w] + R.w] = rowbase + 3;
}

// ---------------------------------------------------------------------------
// K2: perfectly balanced gather — each block owns CHUNK consecutive entries
// of the class-sorted rowidx. (Unchanged — measured.)
// ---------------------------------------------------------------------------
__global__ void __launch_bounds__(256, 4)
chunksum_kernel(const float* __restrict__ features) {
    __shared__ float4 sred[256];
    int tid = threadIdx.x;
    int r4 = tid >> 6;   // row slot 0..3
    int c4 = tid & 63;   // float4 column 0..63
    const float4* __restrict__ f4 = reinterpret_cast<const float4*>(features);

    int s = blockIdx.x * CHUNK;
    int e = s + CHUNK;

    // Largest cls with offsets[cls] <= s  (offsets[0] == 0).
    int lo = 0, hi = NUM_CLASSES - 1;
    while (lo < hi) {
        int mid = (lo + hi + 1) >> 1;
        if (g_offsets[mid] <= s) lo = mid; else hi = mid - 1;
    }
    int cls = lo;
    int pos = s;

    while (pos < e) {
        while (cls < NUM_CLASSES - 1 && g_offsets[cls + 1] <= pos) cls++;
        int cend = g_offsets[cls] + g_counts[cls];
        int segend = min(e, cend);

        float4 a0 = make_float4(0.f, 0.f, 0.f, 0.f);
        float4 a1 = a0, a2 = a0, a3 = a0;

        int i = pos + r4;
        for (; i + 12 < segend; i += 16) {
            int i0 = g_rowidx[i];
            int i1 = g_rowidx[i + 4];
            int i2 = g_rowidx[i + 8];
            int i3 = g_rowidx[i + 12];
            float4 v0 = __ldcs(&f4[(size_t)i0 * 64 + c4]);
            float4 v1 = __ldcs(&f4[(size_t)i1 * 64 + c4]);
            float4 v2 = __ldcs(&f4[(size_t)i2 * 64 + c4]);
            float4 v3 = __ldcs(&f4[(size_t)i3 * 64 + c4]);
            F4ADD(a0, v0); F4ADD(a1, v1); F4ADD(a2, v2); F4ADD(a3, v3);
        }
        for (; i < segend; i += 4) {
            float4 v = __ldcs(&f4[(size_t)g_rowidx[i] * 64 + c4]);
            F4ADD(a0, v);
        }
        F4ADD(a0, a1); F4ADD(a2, a3); F4ADD(a0, a2);

        sred[tid] = a0;
        __syncthreads();
        if (tid < 64) {
            float4 t0 = sred[tid];
            float4 t1 = sred[tid + 64];
            float4 t2 = sred[tid + 128];
            float4 t3 = sred[tid + 192];
            F4ADD(t0, t1); F4ADD(t2, t3); F4ADD(t0, t2);
            red_add_v4(&g_sums[(size_t)cls * FEAT_DIM + tid * 4], t0);
        }
        __syncthreads();
        pos = segend;
    }
}

// ---------------------------------------------------------------------------
// K3: finalize — mean + EMA + output (64000 float4s).
// ---------------------------------------------------------------------------
__global__ void __launch_bounds__(256)
finalize_kernel(const float* __restrict__ centers, float* __restrict__ out) {
    int i = blockIdx.x * blockDim.x + threadIdx.x;      // float4 index
    if (i >= NUM_CLASSES * FEAT_DIM / 4) return;
    int cls = i >> 6;
    int n = g_counts[cls];
    float4 c = reinterpret_cast<const float4*>(centers)[i];
    float4 o = c;
    if (n > 0) {
        float4 t = reinterpret_cast<const float4*>(g_sums)[i];
        float scale = ALPHA / (float)n;
        o.x = (1.0f - ALPHA) * c.x + scale * t.x;
        o.y = (1.0f - ALPHA) * c.y + scale * t.y;
        o.z = (1.0f - ALPHA) * c.z + scale * t.z;
        o.w = (1.0f - ALPHA) * c.w + scale * t.w;
    }
    reinterpret_cast<float4*>(out)[i] = o;
}

// ---------------------------------------------------------------------------
// Launch: features f32 [N,256], labels i32 [N], centers f32 [1000,256].
// ---------------------------------------------------------------------------
extern "C" void kernel_launch(void* const* d_in, const int* in_sizes, int n_in,
                              void* d_out, int out_size) {
    const float* features = (const float*)d_in[0];
    const int* labels     = (const int*)d_in[1];
    const float* centers  = (const float*)d_in[2];
    float* out            = (float*)d_out;

    idxA_kernel<<<NB, NT>>>(labels);
    idxB_kernel<<<NB, NT>>>();
    idxC_kernel<<<NB, NT>>>(labels);
    chunksum_kernel<<<NCHUNK, 256>>>(features);
    finalize_kernel<<<NUM_CLASSES * FEAT_DIM / 4 / 256, 256>>>(centers, out);
}